// round 9
// baseline (speedup 1.0000x reference)
#include <cuda_runtime.h>
#include <cuda_bf16.h>

#define B_    4
#define SEQ_  4096
#define D_    64
#define V_    512
#define BS_   32
#define R_    128          // SEQ/BS
#define PPB_  8256         // panels per batch = R(R+1)/2
#define CHUNK 32           // max panels per gather CTA (run-aligned)
#define PAD   72           // bf16 row pitch (144B): (4g+t) banks, conflict-free

// Scratch (device globals — no allocation allowed)
__device__ float g_scores[(size_t)B_ * SEQ_ * V_];              // [b][m][v]
__device__ __nv_bfloat16 g_qhi[(size_t)B_ * SEQ_ * D_];
__device__ __nv_bfloat16 g_qlo[(size_t)B_ * SEQ_ * D_];
__device__ __nv_bfloat16 g_ehi[(size_t)B_ * V_ * D_];
__device__ __nv_bfloat16 g_elo[(size_t)B_ * V_ * D_];

#define MMA_BF16(c, a, b)                                                     \
    asm volatile(                                                             \
        "mma.sync.aligned.m16n8k16.row.col.f32.bf16.bf16.f32 "               \
        "{%0,%1,%2,%3}, {%4,%5,%6,%7}, {%8,%9}, {%0,%1,%2,%3};"              \
        : "+f"((c)[0]), "+f"((c)[1]), "+f"((c)[2]), "+f"((c)[3])              \
        : "r"((a)[0]), "r"((a)[1]), "r"((a)[2]), "r"((a)[3]),                 \
          "r"((b)[0]), "r"((b)[1]))

// ---------------------------------------------------------------------------
// One-time split: fp32 -> (hi, lo) bf16 planes for q and emb.
// 4 independent float4 per thread (loads issued first -> MLP 4).
// ---------------------------------------------------------------------------
#define NQ4_ (B_ * SEQ_ * D_ / 4)       // 262144
#define NE4_ (B_ * V_ * D_ / 4)         // 32768
#define NT4_ (NQ4_ + NE4_)              // 294912
#define SPLIT_THREADS (NT4_ / 4)        // 73728 -> 288 blocks of 256

__global__ __launch_bounds__(256) void split_kernel(
    const float* __restrict__ q, const float* __restrict__ emb) {
    const int tid0 = blockIdx.x * 256 + threadIdx.x;

    float4 x[4];
    int j[4];
    const float* srcs[4];
#pragma unroll
    for (int u = 0; u < 4; ++u) {
        int i = tid0 + u * SPLIT_THREADS;
        if (i < NQ4_) { srcs[u] = q;   j[u] = i; }
        else          { srcs[u] = emb; j[u] = i - NQ4_; }
        x[u] = ((const float4*)srcs[u])[j[u]];
    }
#pragma unroll
    for (int u = 0; u < 4; ++u) {
        int i = tid0 + u * SPLIT_THREADS;
        __nv_bfloat16 *hi, *lo;
        if (i < NQ4_) { hi = g_qhi; lo = g_qlo; }
        else          { hi = g_ehi; lo = g_elo; }
        float a[4] = {x[u].x, x[u].y, x[u].z, x[u].w};
        __nv_bfloat16 h[4], l[4];
#pragma unroll
        for (int v = 0; v < 4; ++v) {
            h[v] = __float2bfloat16(a[v]);
            l[v] = __float2bfloat16(a[v] - __bfloat162float(h[v]));
        }
        __nv_bfloat162 h01 = __halves2bfloat162(h[0], h[1]);
        __nv_bfloat162 h23 = __halves2bfloat162(h[2], h[3]);
        __nv_bfloat162 l01 = __halves2bfloat162(l[0], l[1]);
        __nv_bfloat162 l23 = __halves2bfloat162(l[2], l[3]);
        uint2 hh, ll;
        hh.x = *(unsigned*)&h01; hh.y = *(unsigned*)&h23;
        ll.x = *(unsigned*)&l01; ll.y = *(unsigned*)&l23;
        *(uint2*)&hi[j[u] * 4] = hh;
        *(uint2*)&lo[j[u] * 4] = ll;
    }
}

// ---------------------------------------------------------------------------
// GEMM via bf16-split tensor cores (round-7 validated): scores = q @ emb^T.
// CTA: 256 threads (8 warps), tile 128(m) x 128(v), full K=64.
// ---------------------------------------------------------------------------
__global__ __launch_bounds__(256) void gemm_mma_kernel() {
    extern __shared__ __nv_bfloat16 sm[];
    __nv_bfloat16* a_hi = sm;                    // [128][PAD]
    __nv_bfloat16* a_lo = a_hi + 128 * PAD;
    __nv_bfloat16* b_hi = a_lo + 128 * PAD;
    __nv_bfloat16* b_lo = b_hi + 128 * PAD;

    const int b = blockIdx.z;
    const int mBase = blockIdx.x * 128;
    const int vBase = blockIdx.y * 128;
    const int tid = threadIdx.x;

    // ---- Copy pre-split planes into padded smem (coalesced uint4) ----
    {
        const uint4* __restrict__ srcs[4] = {
            (const uint4*)(g_qhi + ((size_t)b * SEQ_ + mBase) * D_),
            (const uint4*)(g_qlo + ((size_t)b * SEQ_ + mBase) * D_),
            (const uint4*)(g_ehi + ((size_t)b * V_ + vBase) * D_),
            (const uint4*)(g_elo + ((size_t)b * V_ + vBase) * D_)};
        __nv_bfloat16* dsts[4] = {a_hi, a_lo, b_hi, b_lo};
#pragma unroll
        for (int it = 0; it < 16; ++it) {
            int lin = tid + it * 256;        // 0..4095
            int plane = lin >> 10;           // 1024 uint4 per plane
            int r = (lin >> 3) & 127;        // row
            int ch = lin & 7;                // 8-bf16 chunk
            *(uint4*)&dsts[plane][r * PAD + ch * 8] = srcs[plane][r * 8 + ch];
        }
    }
    __syncthreads();

    // ---- MMA ----
    const int wid = tid >> 5, lane = tid & 31;
    const int wm = wid & 3;      // warp m position (4 x 32 = 128)
    const int wv = wid >> 2;     // warp v position (2 x 64 = 128)
    const int g = lane >> 2;     // group id (row within fragment)
    const int t4 = lane & 3;     // thread-in-group (col pairs)

    float c[2][8][4];
#pragma unroll
    for (int mi = 0; mi < 2; ++mi)
#pragma unroll
        for (int ni = 0; ni < 8; ++ni)
#pragma unroll
            for (int u = 0; u < 4; ++u) c[mi][ni][u] = 0.0f;

#pragma unroll
    for (int ks = 0; ks < 4; ++ks) {
        const int k0 = ks * 16 + 2 * t4;
        unsigned ahi[2][4], alo[2][4];
#pragma unroll
        for (int mi = 0; mi < 2; ++mi) {
            int r0 = wm * 32 + mi * 16 + g;
            ahi[mi][0] = *(unsigned*)&a_hi[r0 * PAD + k0];
            ahi[mi][1] = *(unsigned*)&a_hi[(r0 + 8) * PAD + k0];
            ahi[mi][2] = *(unsigned*)&a_hi[r0 * PAD + k0 + 8];
            ahi[mi][3] = *(unsigned*)&a_hi[(r0 + 8) * PAD + k0 + 8];
            alo[mi][0] = *(unsigned*)&a_lo[r0 * PAD + k0];
            alo[mi][1] = *(unsigned*)&a_lo[(r0 + 8) * PAD + k0];
            alo[mi][2] = *(unsigned*)&a_lo[r0 * PAD + k0 + 8];
            alo[mi][3] = *(unsigned*)&a_lo[(r0 + 8) * PAD + k0 + 8];
        }
#pragma unroll
        for (int ni = 0; ni < 8; ++ni) {
            int n0 = wv * 64 + ni * 8 + g;
            unsigned bhi[2], blo[2];
            bhi[0] = *(unsigned*)&b_hi[n0 * PAD + k0];
            bhi[1] = *(unsigned*)&b_hi[n0 * PAD + k0 + 8];
            blo[0] = *(unsigned*)&b_lo[n0 * PAD + k0];
            blo[1] = *(unsigned*)&b_lo[n0 * PAD + k0 + 8];
#pragma unroll
            for (int mi = 0; mi < 2; ++mi) {
                MMA_BF16(c[mi][ni], ahi[mi], bhi);
                MMA_BF16(c[mi][ni], ahi[mi], blo);
                MMA_BF16(c[mi][ni], alo[mi], bhi);
            }
        }
    }

    // ---- Epilogue: fp32 scores ----
#pragma unroll
    for (int mi = 0; mi < 2; ++mi) {
#pragma unroll
        for (int ni = 0; ni < 8; ++ni) {
            int r0 = mBase + wm * 32 + mi * 16 + g;
            int col = vBase + wv * 64 + ni * 8 + 2 * t4;
            float* dst = g_scores + ((size_t)b * SEQ_ + r0) * V_ + col;
            *(float2*)dst = make_float2(c[mi][ni][0], c[mi][ni][1]);
            *(float2*)(dst + 8 * V_) = make_float2(c[mi][ni][2], c[mi][ni][3]);
        }
    }
}

// ---------------------------------------------------------------------------
// Run-aligned gather. Each CTA owns <=32 panels of ONE (b, rb) run, staging
// the 32 score rows (64 KB) exactly once. 1024 threads, 8 panels/iteration:
// each thread covers 2 int4 (panels sub and sub+4) -> 2x MLP vs round 7.
// ---------------------------------------------------------------------------
__global__ __launch_bounds__(1024) void gather_run_kernel(
    const int* __restrict__ info,
    const int* __restrict__ idxs_batch,
    const int* __restrict__ idxs_row,
    float* __restrict__ out) {
    extern __shared__ float s[];   // 64 KB: 32 rows x 512 floats

    const int x  = blockIdx.x;
    const int bi = x / 320;
    const int xb = x - bi * 320;
    int g, base;
    if (xb < 32)       { g = 0; base = 0;   }
    else if (xb < 96)  { g = 1; base = 32;  }
    else if (xb < 192) { g = 2; base = 96;  }
    else               { g = 3; base = 192; }
    const int rb_idx = (g << 5) + (xb - base) / (g + 1);
    const int c      = (xb - base) % (g + 1);
    const int p_start = bi * PPB_ + (rb_idx * (rb_idx + 1)) / 2 + c * CHUNK;
    const int count   = min(CHUNK, rb_idx + 1 - c * CHUNK);

    const int b  = __ldg(&idxs_batch[p_start]);
    const int rb = __ldg(&idxs_row[p_start]);

    const int tid = threadIdx.x;
    const int sub = tid >> 8;      // 0..3; thread also covers sub+4
    const int t   = tid & 255;     // int4 position within panel
    const float* srow = s + (t >> 3) * V_;
    const int4* __restrict__ ip = (const int4*)info;
    float4* __restrict__ op = (float4*)out;

    // Prefetch first iteration's index vectors
    int4 idx0, idx1;
    if (sub < count)
        idx0 = __ldcs(&ip[(size_t)(p_start + sub) * 256 + t]);
    if (sub + 4 < count)
        idx1 = __ldcs(&ip[(size_t)(p_start + sub + 4) * 256 + t]);

    // Stage the 32 score rows (64 KB), 4 float4 per thread
    {
        const float4* __restrict__ src = (const float4*)(
            g_scores + ((size_t)b * SEQ_ + rb * BS_) * V_);
        float4* dst = (float4*)s;
#pragma unroll
        for (int i = 0; i < 4; ++i)
            dst[tid + i * 1024] = src[tid + i * 1024];
    }
    __syncthreads();

    for (int pp = 0; pp < count; pp += 8) {
        const int p0 = pp + sub;        // first panel this thread serves
        const int p1 = pp + sub + 4;    // second panel
        // Prefetch next iteration
        int4 n0, n1;
        if (p0 + 8 < count) n0 = __ldcs(&ip[(size_t)(p_start + p0 + 8) * 256 + t]);
        if (p1 + 8 < count) n1 = __ldcs(&ip[(size_t)(p_start + p1 + 8) * 256 + t]);

        if (p0 < count) {
            float4 o;
            o.x = srow[idx0.x];
            o.y = srow[idx0.y];
            o.z = srow[idx0.z];
            o.w = srow[idx0.w];
            __stcs(&op[(size_t)(p_start + p0) * 256 + t], o);
        }
        if (p1 < count) {
            float4 o;
            o.x = srow[idx1.x];
            o.y = srow[idx1.y];
            o.z = srow[idx1.z];
            o.w = srow[idx1.w];
            __stcs(&op[(size_t)(p_start + p1) * 256 + t], o);
        }
        idx0 = n0;
        idx1 = n1;
    }
}

// ---------------------------------------------------------------------------
// Generic fallback gather (any P / structure).
// ---------------------------------------------------------------------------
__global__ __launch_bounds__(256) void gather_fallback_kernel(
    const int* __restrict__ info,
    const int* __restrict__ idxs_batch,
    const int* __restrict__ idxs_row,
    float* __restrict__ out,
    int P) {
    extern __shared__ float s[];
    const int p0 = blockIdx.x * 16;
    if (p0 >= P) return;
    const int pend = min(p0 + 16, P);
    const int tid = threadIdx.x;
    const float* srow = s + (tid >> 3) * V_;

    int cached = -1;
    int4 idx = ((const int4*)(info + (size_t)p0 * 1024))[tid];
    for (int p = p0; p < pend; ++p) {
        int4 idx_next;
        if (p + 1 < pend)
            idx_next = ((const int4*)(info + (size_t)(p + 1) * 1024))[tid];
        const int b  = __ldg(&idxs_batch[p]);
        const int rb = __ldg(&idxs_row[p]);
        const int key = (b << 16) | rb;
        if (key != cached) {
            __syncthreads();
            const float4* __restrict__ src = (const float4*)(
                g_scores + ((size_t)b * SEQ_ + rb * BS_) * V_);
            float4* dst = (float4*)s;
#pragma unroll
            for (int t2 = 0; t2 < 16; ++t2)
                dst[tid + t2 * 256] = src[tid + t2 * 256];
            cached = key;
            __syncthreads();
        }
        float4 o;
        o.x = srow[idx.x];
        o.y = srow[idx.y];
        o.z = srow[idx.z];
        o.w = srow[idx.w];
        ((float4*)(out + (size_t)p * 1024))[tid] = o;
        idx = idx_next;
    }
}

// ---------------------------------------------------------------------------
extern "C" void kernel_launch(void* const* d_in, const int* in_sizes, int n_in,
                              void* d_out, int out_size) {
    const float* q    = (const float*)d_in[0];
    const float* emb  = (const float*)d_in[1];
    const int*   info = (const int*)d_in[2];
    const int*   idxb = (const int*)d_in[3];
    const int*   idxr = (const int*)d_in[4];
    float* out = (float*)d_out;
    const int P = in_sizes[3];

    const int gemm_smem = 4 * 128 * PAD * (int)sizeof(__nv_bfloat16);  // 72 KB

    static int init_done = 0;
    if (!init_done) {
        cudaFuncSetAttribute(gemm_mma_kernel,
                             cudaFuncAttributeMaxDynamicSharedMemorySize,
                             gemm_smem);
        cudaFuncSetAttribute(gather_run_kernel,
                             cudaFuncAttributeMaxDynamicSharedMemorySize,
                             BS_ * V_ * sizeof(float));
        cudaFuncSetAttribute(gather_fallback_kernel,
                             cudaFuncAttributeMaxDynamicSharedMemorySize,
                             BS_ * V_ * sizeof(float));
        init_done = 1;
    }

    split_kernel<<<SPLIT_THREADS / 256, 256>>>(q, emb);

    gemm_mma_kernel<<<dim3(SEQ_ / 128, V_ / 128, B_), 256, gemm_smem>>>();

    if (P == B_ * PPB_) {
        gather_run_kernel<<<B_ * 320, 1024, BS_ * V_ * sizeof(float)>>>(
            info, idxb, idxr, out);
    } else {
        gather_fallback_kernel<<<(P + 15) / 16, 256, BS_ * V_ * sizeof(float)>>>(
            info, idxb, idxr, out, P);
    }
}

// round 10
// speedup vs baseline: 1.2791x; 1.2791x over previous
#include <cuda_runtime.h>
#include <cuda_bf16.h>

#define B_    4
#define SEQ_  4096
#define D_    64
#define V_    512
#define BS_   32
#define R_    128          // SEQ/BS
#define PPB_  8256         // panels per batch = R(R+1)/2
#define CHUNK 32           // max panels per gather CTA (run-aligned)
#define PAD   72           // bf16 row pitch (144B): conflict-free frag loads

// Scratch (device globals — no allocation allowed)
__device__ float g_scores[(size_t)B_ * SEQ_ * V_];              // [b][m][v]

#define MMA_BF16(c, a, b)                                                     \
    asm volatile(                                                             \
        "mma.sync.aligned.m16n8k16.row.col.f32.bf16.bf16.f32 "               \
        "{%0,%1,%2,%3}, {%4,%5,%6,%7}, {%8,%9}, {%0,%1,%2,%3};"              \
        : "+f"((c)[0]), "+f"((c)[1]), "+f"((c)[2]), "+f"((c)[3])              \
        : "r"((a)[0]), "r"((a)[1]), "r"((a)[2]), "r"((a)[3]),                 \
          "r"((b)[0]), "r"((b)[1]))

// Split a float4 into hi/lo bf16 packs (4 bf16 = 8 bytes each).
__device__ __forceinline__ void split4(float4 x, uint2& h, uint2& l) {
    float a[4] = {x.x, x.y, x.z, x.w};
    __nv_bfloat16 hh[4], ll[4];
#pragma unroll
    for (int u = 0; u < 4; ++u) {
        hh[u] = __float2bfloat16(a[u]);
        ll[u] = __float2bfloat16(a[u] - __bfloat162float(hh[u]));
    }
    __nv_bfloat162 h0 = __halves2bfloat162(hh[0], hh[1]);
    __nv_bfloat162 h1 = __halves2bfloat162(hh[2], hh[3]);
    __nv_bfloat162 l0 = __halves2bfloat162(ll[0], ll[1]);
    __nv_bfloat162 l1 = __halves2bfloat162(ll[2], ll[3]);
    h.x = *(unsigned*)&h0; h.y = *(unsigned*)&h1;
    l.x = *(unsigned*)&l0; l.y = *(unsigned*)&l1;
}

// ---------------------------------------------------------------------------
// Fused split + GEMM via bf16-split tensor cores: scores = q @ emb^T.
// x = hi + lo; x*y ~= hi*hi + hi*lo + lo*hi (validated: rel_err ~4.5e-6).
// CTA: 256 threads (8 warps), tile 128(m) x 256(v), full K=64, 2 CTAs/SM,
// grid 256 = one wave. fp32->bf16 split happens in the prologue (the
// standalone split kernel is gone; q converted <=2x, emb 8x — trivial).
// ---------------------------------------------------------------------------
__global__ __launch_bounds__(256, 2) void gemm_fused_kernel(
    const float* __restrict__ q, const float* __restrict__ emb) {
    extern __shared__ __nv_bfloat16 sm[];
    __nv_bfloat16* a_hi = sm;                     // [128][PAD]
    __nv_bfloat16* a_lo = a_hi + 128 * PAD;
    __nv_bfloat16* b_hi = a_lo + 128 * PAD;       // [256][PAD]
    __nv_bfloat16* b_lo = b_hi + 256 * PAD;

    const int b = blockIdx.z;
    const int mBase = blockIdx.x * 128;
    const int vBase = blockIdx.y * 256;
    const int tid = threadIdx.x;

    // ---- Prologue: load fp32 tiles, split to hi/lo bf16 in smem ----
    const float4* __restrict__ qsrc =
        (const float4*)(q + ((size_t)b * SEQ_ + mBase) * D_);
#pragma unroll
    for (int i = 0; i < 8; ++i) {
        int idx = tid + i * 256;          // 0..2047 = 128 rows x 16 float4
        int r = idx >> 4, c4 = (idx & 15) * 4;
        uint2 h, l;
        split4(qsrc[idx], h, l);
        *(uint2*)&a_hi[r * PAD + c4] = h;
        *(uint2*)&a_lo[r * PAD + c4] = l;
    }
    const float4* __restrict__ esrc =
        (const float4*)(emb + ((size_t)b * V_ + vBase) * D_);
#pragma unroll
    for (int i = 0; i < 16; ++i) {
        int idx = tid + i * 256;          // 0..4095 = 256 rows x 16 float4
        int r = idx >> 4, c4 = (idx & 15) * 4;
        uint2 h, l;
        split4(esrc[idx], h, l);
        *(uint2*)&b_hi[r * PAD + c4] = h;
        *(uint2*)&b_lo[r * PAD + c4] = l;
    }
    __syncthreads();

    // ---- MMA: warp tile 32(m) x 128(v), two 64-col v-chunks ----
    const int wid = tid >> 5, lane = tid & 31;
    const int wm = wid & 3;      // warp m position (4 x 32 = 128)
    const int wv = wid >> 2;     // warp v position (2 x 128 = 256)
    const int g = lane >> 2;     // group id (row within fragment)
    const int t4 = lane & 3;     // thread-in-group (col pairs)

#pragma unroll
    for (int vc = 0; vc < 2; ++vc) {
        float c[2][8][4];
#pragma unroll
        for (int mi = 0; mi < 2; ++mi)
#pragma unroll
            for (int ni = 0; ni < 8; ++ni)
#pragma unroll
                for (int u = 0; u < 4; ++u) c[mi][ni][u] = 0.0f;

#pragma unroll
        for (int ks = 0; ks < 4; ++ks) {
            const int k0 = ks * 16 + 2 * t4;
            unsigned ahi[2][4], alo[2][4];
#pragma unroll
            for (int mi = 0; mi < 2; ++mi) {
                int r0 = wm * 32 + mi * 16 + g;
                ahi[mi][0] = *(unsigned*)&a_hi[r0 * PAD + k0];
                ahi[mi][1] = *(unsigned*)&a_hi[(r0 + 8) * PAD + k0];
                ahi[mi][2] = *(unsigned*)&a_hi[r0 * PAD + k0 + 8];
                ahi[mi][3] = *(unsigned*)&a_hi[(r0 + 8) * PAD + k0 + 8];
                alo[mi][0] = *(unsigned*)&a_lo[r0 * PAD + k0];
                alo[mi][1] = *(unsigned*)&a_lo[(r0 + 8) * PAD + k0];
                alo[mi][2] = *(unsigned*)&a_lo[r0 * PAD + k0 + 8];
                alo[mi][3] = *(unsigned*)&a_lo[(r0 + 8) * PAD + k0 + 8];
            }
#pragma unroll
            for (int ni = 0; ni < 8; ++ni) {
                int n0 = wv * 128 + vc * 64 + ni * 8 + g;
                unsigned bhi[2], blo[2];
                bhi[0] = *(unsigned*)&b_hi[n0 * PAD + k0];
                bhi[1] = *(unsigned*)&b_hi[n0 * PAD + k0 + 8];
                blo[0] = *(unsigned*)&b_lo[n0 * PAD + k0];
                blo[1] = *(unsigned*)&b_lo[n0 * PAD + k0 + 8];
#pragma unroll
                for (int mi = 0; mi < 2; ++mi) {
                    MMA_BF16(c[mi][ni], ahi[mi], bhi);
                    MMA_BF16(c[mi][ni], ahi[mi], blo);
                    MMA_BF16(c[mi][ni], alo[mi], bhi);
                }
            }
        }

        // ---- Epilogue for this v-chunk ----
#pragma unroll
        for (int mi = 0; mi < 2; ++mi) {
#pragma unroll
            for (int ni = 0; ni < 8; ++ni) {
                int r0 = mBase + wm * 32 + mi * 16 + g;
                int col = vBase + wv * 128 + vc * 64 + ni * 8 + 2 * t4;
                float* dst = g_scores + ((size_t)b * SEQ_ + r0) * V_ + col;
                *(float2*)dst = make_float2(c[mi][ni][0], c[mi][ni][1]);
                *(float2*)(dst + 8 * V_) = make_float2(c[mi][ni][2], c[mi][ni][3]);
            }
        }
    }
}

// ---------------------------------------------------------------------------
// Run-aligned gather (exact round-7 best: 49.2us). Each CTA owns <=32 panels
// of ONE (b, rb) run, staging the 32 score rows (64 KB) exactly once.
// 1024 threads: 4 panels/iter, 4 elems/thread; streaming hints on info/out.
// ---------------------------------------------------------------------------
__global__ __launch_bounds__(1024) void gather_run_kernel(
    const int* __restrict__ info,
    const int* __restrict__ idxs_batch,
    const int* __restrict__ idxs_row,
    float* __restrict__ out) {
    extern __shared__ float s[];   // 64 KB: 32 rows x 512 floats

    const int x  = blockIdx.x;
    const int bi = x / 320;
    const int xb = x - bi * 320;
    int g, base;
    if (xb < 32)       { g = 0; base = 0;   }
    else if (xb < 96)  { g = 1; base = 32;  }
    else if (xb < 192) { g = 2; base = 96;  }
    else               { g = 3; base = 192; }
    const int rb_idx = (g << 5) + (xb - base) / (g + 1);
    const int c      = (xb - base) % (g + 1);
    const int p_start = bi * PPB_ + (rb_idx * (rb_idx + 1)) / 2 + c * CHUNK;
    const int count   = min(CHUNK, rb_idx + 1 - c * CHUNK);

    const int b  = __ldg(&idxs_batch[p_start]);
    const int rb = __ldg(&idxs_row[p_start]);

    const int tid = threadIdx.x;
    const int sub = tid >> 8;      // which of 4 panels this iteration (0..3)
    const int t   = tid & 255;     // position within panel (4 elems)
    const float* srow = s + (t >> 3) * V_;

    int4 idx;
    if (sub < count)
        idx = __ldcs(&((const int4*)info)[(size_t)(p_start + sub) * 256 + t]);

    {
        const float4* __restrict__ src = (const float4*)(
            g_scores + ((size_t)b * SEQ_ + rb * BS_) * V_);
        float4* dst = (float4*)s;
#pragma unroll
        for (int i = 0; i < 4; ++i)
            dst[tid + i * 1024] = src[tid + i * 1024];
    }
    __syncthreads();

    for (int pp = 0; pp < count; pp += 4) {
        const int pcur = pp + sub;
        const int pnext = pcur + 4;
        int4 idxn;
        if (pnext < count)
            idxn = __ldcs(&((const int4*)info)[(size_t)(p_start + pnext) * 256 + t]);

        if (pcur < count) {
            float4 o;
            o.x = srow[idx.x];
            o.y = srow[idx.y];
            o.z = srow[idx.z];
            o.w = srow[idx.w];
            __stcs(&((float4*)out)[(size_t)(p_start + pcur) * 256 + t], o);
        }
        idx = idxn;
    }
}

// ---------------------------------------------------------------------------
// Generic fallback gather (any P / structure).
// ---------------------------------------------------------------------------
__global__ __launch_bounds__(256) void gather_fallback_kernel(
    const int* __restrict__ info,
    const int* __restrict__ idxs_batch,
    const int* __restrict__ idxs_row,
    float* __restrict__ out,
    int P) {
    extern __shared__ float s[];
    const int p0 = blockIdx.x * 16;
    if (p0 >= P) return;
    const int pend = min(p0 + 16, P);
    const int tid = threadIdx.x;
    const float* srow = s + (tid >> 3) * V_;

    int cached = -1;
    int4 idx = ((const int4*)(info + (size_t)p0 * 1024))[tid];
    for (int p = p0; p < pend; ++p) {
        int4 idx_next;
        if (p + 1 < pend)
            idx_next = ((const int4*)(info + (size_t)(p + 1) * 1024))[tid];
        const int b  = __ldg(&idxs_batch[p]);
        const int rb = __ldg(&idxs_row[p]);
        const int key = (b << 16) | rb;
        if (key != cached) {
            __syncthreads();
            const float4* __restrict__ src = (const float4*)(
                g_scores + ((size_t)b * SEQ_ + rb * BS_) * V_);
            float4* dst = (float4*)s;
#pragma unroll
            for (int t2 = 0; t2 < 16; ++t2)
                dst[tid + t2 * 256] = src[tid + t2 * 256];
            cached = key;
            __syncthreads();
        }
        float4 o;
        o.x = srow[idx.x];
        o.y = srow[idx.y];
        o.z = srow[idx.z];
        o.w = srow[idx.w];
        ((float4*)(out + (size_t)p * 1024))[tid] = o;
        idx = idx_next;
    }
}

// ---------------------------------------------------------------------------
extern "C" void kernel_launch(void* const* d_in, const int* in_sizes, int n_in,
                              void* d_out, int out_size) {
    const float* q    = (const float*)d_in[0];
    const float* emb  = (const float*)d_in[1];
    const int*   info = (const int*)d_in[2];
    const int*   idxb = (const int*)d_in[3];
    const int*   idxr = (const int*)d_in[4];
    float* out = (float*)d_out;
    const int P = in_sizes[3];

    const int gemm_smem = (128 * 2 + 256 * 2) * PAD * (int)sizeof(__nv_bfloat16);
    // = 768 * 72 * 2 = 110592 B (108 KB) -> 2 CTAs/SM

    static int init_done = 0;
    if (!init_done) {
        cudaFuncSetAttribute(gemm_fused_kernel,
                             cudaFuncAttributeMaxDynamicSharedMemorySize,
                             gemm_smem);
        cudaFuncSetAttribute(gather_run_kernel,
                             cudaFuncAttributeMaxDynamicSharedMemorySize,
                             BS_ * V_ * sizeof(float));
        cudaFuncSetAttribute(gather_fallback_kernel,
                             cudaFuncAttributeMaxDynamicSharedMemorySize,
                             BS_ * V_ * sizeof(float));
        init_done = 1;
    }

    gemm_fused_kernel<<<dim3(SEQ_ / 128, V_ / 256, B_), 256, gemm_smem>>>(q, emb);

    if (P == B_ * PPB_) {
        gather_run_kernel<<<B_ * 320, 1024, BS_ * V_ * sizeof(float)>>>(
            info, idxb, idxr, out);
    } else {
        gather_fallback_kernel<<<(P + 15) / 16, 256, BS_ * V_ * sizeof(float)>>>(
            info, idxb, idxr, out, P);
    }
}